// round 5
// baseline (speedup 1.0000x reference)
#include <cuda_runtime.h>
#include <math.h>

#define BDIM 8192
#define HDIM 1024
#define ADIM 1024
#define RSLICE 64
#define ROWS_PER_SLICE (BDIM / RSLICE)   // 128

// ---- scratch (device globals: no allocations allowed) ----
__device__ float d_Y[(size_t)BDIM * HDIM];            // 32 MB
__device__ float d_S[(size_t)BDIM * BDIM];            // 256 MB (scores -> exp in place)
__device__ float d_ctx[(size_t)BDIM * HDIM];          // 32 MB
__device__ float d_part[(size_t)RSLICE * BDIM];       // partials
__device__ float d_colmax[BDIM];
__device__ float d_colinv[BDIM];

// ---- packed f32x2 helpers (Blackwell-only PTX; ptxas never emits these) ----
__device__ __forceinline__ void fma2(unsigned long long& d, unsigned long long a,
                                     unsigned long long b) {
    asm("fma.rn.f32x2 %0, %1, %2, %0;" : "+l"(d) : "l"(a), "l"(b));
}
__device__ __forceinline__ unsigned long long bcast2(float x) {
    unsigned long long r;
    asm("mov.b64 %0, {%1, %1};" : "=l"(r) : "f"(x));
    return r;
}
__device__ __forceinline__ float2 unpack2(unsigned long long v) {
    float2 f;
    asm("mov.b64 {%0, %1}, %2;" : "=f"(f.x), "=f"(f.y) : "l"(v));
    return f;
}

// 8x8 fragment as 8x4 packed pairs (pair along n).
__device__ __forceinline__ void frag_fma(unsigned long long acc2[8][4],
                                         const float* __restrict__ a_ptr,
                                         const float* __restrict__ b_ptr) {
    float4 ta0 = *(const float4*)(a_ptr);
    float4 ta1 = *(const float4*)(a_ptr + 4);
    ulonglong2 tb0 = *(const ulonglong2*)(b_ptr);
    ulonglong2 tb1 = *(const ulonglong2*)(b_ptr + 4);
    unsigned long long b2[4] = {tb0.x, tb0.y, tb1.x, tb1.y};
    float a[8] = {ta0.x, ta0.y, ta0.z, ta0.w, ta1.x, ta1.y, ta1.z, ta1.w};
    #pragma unroll
    for (int i = 0; i < 8; i++) {
        unsigned long long a2 = bcast2(a[i]);
        #pragma unroll
        for (int j = 0; j < 4; j++) fma2(acc2[i][j], a2, b2[j]);
    }
}

// ============================================================
// NT GEMM (double-buffered): C[m][n] = sum_k A[m][k]*B[n][k] (+bias)
// BM=BN=128, BK=16, 256 threads, 8x8/thread, 2 CTAs/SM.
// bias==nullptr identifies the streaming S GEMM -> evict-first stores.
// ============================================================
__global__ void __launch_bounds__(256, 2)
gemm_nt_kernel(const float* __restrict__ A, const float* __restrict__ B,
               float* __restrict__ C, int K, int lda, int ldb, int ldc,
               const float* __restrict__ bias)
{
    __shared__ float As[2][16][132];
    __shared__ float Bs[2][16][132];
    const int tid = threadIdx.x;
    const int tx = tid & 15;          // n-dir
    const int ty = tid >> 4;          // m-dir
    const int m0 = blockIdx.y * 128;
    const int n0 = blockIdx.x * 128;

    const int r0 = tid >> 2,         c0 = tid & 3;
    const int r1 = (tid + 256) >> 2, c1 = (tid + 256) & 3;

    unsigned long long acc2[8][4];
    const unsigned long long z2 = bcast2(0.f);
    #pragma unroll
    for (int i = 0; i < 8; i++)
        #pragma unroll
        for (int j = 0; j < 4; j++) acc2[i][j] = z2;

    const float* Ap = A + (size_t)m0 * lda;
    const float* Bp = B + (size_t)n0 * ldb;

    float4 pa0, pa1, pb0, pb1;
    pa0 = *(const float4*)(Ap + (size_t)r0 * lda + c0 * 4);
    pa1 = *(const float4*)(Ap + (size_t)r1 * lda + c1 * 4);
    pb0 = *(const float4*)(Bp + (size_t)r0 * ldb + c0 * 4);
    pb1 = *(const float4*)(Bp + (size_t)r1 * ldb + c1 * 4);

    int buf = 0;
    const int NT = K / 16;
    for (int kt = 0; kt < NT; kt++) {
        As[buf][c0*4+0][r0] = pa0.x; As[buf][c0*4+1][r0] = pa0.y;
        As[buf][c0*4+2][r0] = pa0.z; As[buf][c0*4+3][r0] = pa0.w;
        As[buf][c1*4+0][r1] = pa1.x; As[buf][c1*4+1][r1] = pa1.y;
        As[buf][c1*4+2][r1] = pa1.z; As[buf][c1*4+3][r1] = pa1.w;
        Bs[buf][c0*4+0][r0] = pb0.x; Bs[buf][c0*4+1][r0] = pb0.y;
        Bs[buf][c0*4+2][r0] = pb0.z; Bs[buf][c0*4+3][r0] = pb0.w;
        Bs[buf][c1*4+0][r1] = pb1.x; Bs[buf][c1*4+1][r1] = pb1.y;
        Bs[buf][c1*4+2][r1] = pb1.z; Bs[buf][c1*4+3][r1] = pb1.w;
        __syncthreads();

        if (kt + 1 < NT) {
            int k0 = (kt + 1) * 16;
            pa0 = *(const float4*)(Ap + (size_t)r0 * lda + k0 + c0 * 4);
            pa1 = *(const float4*)(Ap + (size_t)r1 * lda + k0 + c1 * 4);
            pb0 = *(const float4*)(Bp + (size_t)r0 * ldb + k0 + c0 * 4);
            pb1 = *(const float4*)(Bp + (size_t)r1 * ldb + k0 + c1 * 4);
        }

        #pragma unroll
        for (int k = 0; k < 16; k++)
            frag_fma(acc2, &As[buf][k][ty*8], &Bs[buf][k][tx*8]);

        buf ^= 1;
    }

    #pragma unroll
    for (int i = 0; i < 8; i++) {
        int m = m0 + ty * 8 + i;
        #pragma unroll
        for (int j = 0; j < 4; j++) {
            int n = n0 + tx * 8 + j * 2;
            float2 v = unpack2(acc2[i][j]);
            if (bias) {
                v.x += __ldg(&bias[n]); v.y += __ldg(&bias[n + 1]);
                *(float2*)&C[(size_t)m * ldc + n] = v;
            } else {
                // streaming 256MB S output: evict-first, don't thrash L2
                __stcs((float2*)&C[(size_t)m * ldc + n], v);
            }
        }
    }
}

// ============================================================
// TN GEMM with row scale (double-buffered):
// C[m][n] = scale[m] * sum_k A[k][m]*B[k][n]
// ============================================================
__global__ void __launch_bounds__(256, 2)
gemm_tn_scale_kernel(const float* __restrict__ A, const float* __restrict__ B,
                     float* __restrict__ C, int K, int lda, int ldb, int ldc,
                     const float* __restrict__ rowscale)
{
    __shared__ float As[2][16][128];
    __shared__ float Bs[2][16][128];
    const int tid = threadIdx.x;
    const int tx = tid & 15;
    const int ty = tid >> 4;
    const int m0 = blockIdx.y * 128;
    const int n0 = blockIdx.x * 128;

    const int r0 = tid >> 5,         c0 = tid & 31;
    const int r1 = (tid + 256) >> 5, c1 = (tid + 256) & 31;

    unsigned long long acc2[8][4];
    const unsigned long long z2 = bcast2(0.f);
    #pragma unroll
    for (int i = 0; i < 8; i++)
        #pragma unroll
        for (int j = 0; j < 4; j++) acc2[i][j] = z2;

    float4 pa0, pa1, pb0, pb1;
    pa0 = *(const float4*)(A + (size_t)r0 * lda + m0 + c0 * 4);
    pa1 = *(const float4*)(A + (size_t)r1 * lda + m0 + c1 * 4);
    pb0 = *(const float4*)(B + (size_t)r0 * ldb + n0 + c0 * 4);
    pb1 = *(const float4*)(B + (size_t)r1 * ldb + n0 + c1 * 4);

    int buf = 0;
    const int NT = K / 16;
    for (int kt = 0; kt < NT; kt++) {
        *(float4*)&As[buf][r0][c0*4] = pa0;
        *(float4*)&As[buf][r1][c1*4] = pa1;
        *(float4*)&Bs[buf][r0][c0*4] = pb0;
        *(float4*)&Bs[buf][r1][c1*4] = pb1;
        __syncthreads();

        if (kt + 1 < NT) {
            int k0 = (kt + 1) * 16;
            pa0 = *(const float4*)(A + (size_t)(k0 + r0) * lda + m0 + c0 * 4);
            pa1 = *(const float4*)(A + (size_t)(k0 + r1) * lda + m0 + c1 * 4);
            pb0 = *(const float4*)(B + (size_t)(k0 + r0) * ldb + n0 + c0 * 4);
            pb1 = *(const float4*)(B + (size_t)(k0 + r1) * ldb + n0 + c1 * 4);
        }

        #pragma unroll
        for (int k = 0; k < 16; k++)
            frag_fma(acc2, &As[buf][k][ty*8], &Bs[buf][k][tx*8]);

        buf ^= 1;
    }

    #pragma unroll
    for (int i = 0; i < 8; i++) {
        int m = m0 + ty * 8 + i;
        float s = __ldg(&rowscale[m]);
        #pragma unroll
        for (int j = 0; j < 4; j++) {
            int n = n0 + tx * 8 + j * 2;
            float2 v = unpack2(acc2[i][j]);
            v.x *= s; v.y *= s;
            *(float2*)&C[(size_t)m * ldc + n] = v;
        }
    }
}

// ============================================================
// Output GEMM (double-buffered): out = tanh([attender|ctx] @ W^T + b)
// A-source switches per K-tile (tiles never straddle H).
// ============================================================
__global__ void __launch_bounds__(256, 2)
gemm_out_tanh_kernel(const float* __restrict__ attender, const float* __restrict__ ctx,
                     const float* __restrict__ W, const float* __restrict__ bias,
                     float* __restrict__ C)
{
    __shared__ float As[2][16][132];
    __shared__ float Bs[2][16][132];
    const int tid = threadIdx.x;
    const int tx = tid & 15;
    const int ty = tid >> 4;
    const int m0 = blockIdx.y * 128;
    const int n0 = blockIdx.x * 128;
    const int K  = 2 * HDIM;

    const int r0 = tid >> 2,         c0 = tid & 3;
    const int r1 = (tid + 256) >> 2, c1 = (tid + 256) & 3;

    unsigned long long acc2[8][4];
    const unsigned long long z2 = bcast2(0.f);
    #pragma unroll
    for (int i = 0; i < 8; i++)
        #pragma unroll
        for (int j = 0; j < 4; j++) acc2[i][j] = z2;

    const float* Wp = W + (size_t)n0 * K;

    float4 pa0, pa1, pb0, pb1;
    pa0 = *(const float4*)(attender + (size_t)(m0 + r0) * HDIM + c0 * 4);
    pa1 = *(const float4*)(attender + (size_t)(m0 + r1) * HDIM + c1 * 4);
    pb0 = *(const float4*)(Wp + (size_t)r0 * K + c0 * 4);
    pb1 = *(const float4*)(Wp + (size_t)r1 * K + c1 * 4);

    int buf = 0;
    const int NT = K / 16;
    for (int kt = 0; kt < NT; kt++) {
        As[buf][c0*4+0][r0] = pa0.x; As[buf][c0*4+1][r0] = pa0.y;
        As[buf][c0*4+2][r0] = pa0.z; As[buf][c0*4+3][r0] = pa0.w;
        As[buf][c1*4+0][r1] = pa1.x; As[buf][c1*4+1][r1] = pa1.y;
        As[buf][c1*4+2][r1] = pa1.z; As[buf][c1*4+3][r1] = pa1.w;
        Bs[buf][c0*4+0][r0] = pb0.x; Bs[buf][c0*4+1][r0] = pb0.y;
        Bs[buf][c0*4+2][r0] = pb0.z; Bs[buf][c0*4+3][r0] = pb0.w;
        Bs[buf][c1*4+0][r1] = pb1.x; Bs[buf][c1*4+1][r1] = pb1.y;
        Bs[buf][c1*4+2][r1] = pb1.z; Bs[buf][c1*4+3][r1] = pb1.w;
        __syncthreads();

        if (kt + 1 < NT) {
            int k0 = (kt + 1) * 16;
            const float* Asrc; int koff;
            if (k0 < HDIM) { Asrc = attender; koff = k0; }
            else           { Asrc = ctx;      koff = k0 - HDIM; }
            pa0 = *(const float4*)(Asrc + (size_t)(m0 + r0) * HDIM + koff + c0 * 4);
            pa1 = *(const float4*)(Asrc + (size_t)(m0 + r1) * HDIM + koff + c1 * 4);
            pb0 = *(const float4*)(Wp + (size_t)r0 * K + k0 + c0 * 4);
            pb1 = *(const float4*)(Wp + (size_t)r1 * K + k0 + c1 * 4);
        }

        #pragma unroll
        for (int k = 0; k < 16; k++)
            frag_fma(acc2, &As[buf][k][ty*8], &Bs[buf][k][tx*8]);

        buf ^= 1;
    }

    #pragma unroll
    for (int i = 0; i < 8; i++) {
        int m = m0 + ty * 8 + i;
        #pragma unroll
        for (int j = 0; j < 4; j++) {
            int n = n0 + tx * 8 + j * 2;
            float2 v = unpack2(acc2[i][j]);
            v.x = tanhf(v.x + __ldg(&bias[n]));
            v.y = tanhf(v.y + __ldg(&bias[n + 1]));
            *(float2*)&C[(size_t)m * ADIM + n] = v;
        }
    }
}

// ============================================================
// Column softmax (softmax over rows i, per column j), float4-vectorized.
// Deterministic 2-stage reductions; S row-major [BDIM x BDIM].
// Streaming reads of S use __ldcs (evict-first; S >> L2).
// ============================================================
__global__ void colmax_part_kernel()
{
    int j4 = blockIdx.x * blockDim.x + threadIdx.x;   // float4 col index
    int ys = blockIdx.y;
    size_t base = ((size_t)ys * ROWS_PER_SLICE * BDIM) / 4 + j4;
    const float4* S4 = (const float4*)d_S;
    float4 m = make_float4(-INFINITY, -INFINITY, -INFINITY, -INFINITY);
    for (int i = 0; i < ROWS_PER_SLICE; i++) {
        float4 v = __ldcs(&S4[base + (size_t)i * (BDIM / 4)]);
        m.x = fmaxf(m.x, v.x); m.y = fmaxf(m.y, v.y);
        m.z = fmaxf(m.z, v.z); m.w = fmaxf(m.w, v.w);
    }
    ((float4*)d_part)[(size_t)ys * (BDIM / 4) + j4] = m;
}

__global__ void colmax_reduce_kernel()
{
    int j4 = blockIdx.x * blockDim.x + threadIdx.x;
    const float4* P4 = (const float4*)d_part;
    float4 m = make_float4(-INFINITY, -INFINITY, -INFINITY, -INFINITY);
    #pragma unroll 8
    for (int r = 0; r < RSLICE; r++) {
        float4 v = P4[(size_t)r * (BDIM / 4) + j4];
        m.x = fmaxf(m.x, v.x); m.y = fmaxf(m.y, v.y);
        m.z = fmaxf(m.z, v.z); m.w = fmaxf(m.w, v.w);
    }
    ((float4*)d_colmax)[j4] = m;
}

__global__ void expsum_part_kernel()
{
    int j4 = blockIdx.x * blockDim.x + threadIdx.x;
    int ys = blockIdx.y;
    float4* S4 = (float4*)d_S;
    size_t base = ((size_t)ys * ROWS_PER_SLICE * BDIM) / 4 + j4;
    float4 mx = ((const float4*)d_colmax)[j4];
    float4 s = make_float4(0.f, 0.f, 0.f, 0.f);
    for (int i = 0; i < ROWS_PER_SLICE; i++) {
        size_t idx = base + (size_t)i * (BDIM / 4);
        float4 v = __ldcs(&S4[idx]);      // score read: last use of this value
        v.x = __expf(v.x - mx.x); v.y = __expf(v.y - mx.y);
        v.z = __expf(v.z - mx.z); v.w = __expf(v.w - mx.w);
        S4[idx] = v;                      // exp value: re-read by ctx GEMM, keep default policy
        s.x += v.x; s.y += v.y; s.z += v.z; s.w += v.w;
    }
    ((float4*)d_part)[(size_t)ys * (BDIM / 4) + j4] = s;
}

__global__ void colsum_reduce_kernel()
{
    int j4 = blockIdx.x * blockDim.x + threadIdx.x;
    const float4* P4 = (const float4*)d_part;
    float4 s = make_float4(0.f, 0.f, 0.f, 0.f);
    #pragma unroll 8
    for (int r = 0; r < RSLICE; r++) {
        float4 v = P4[(size_t)r * (BDIM / 4) + j4];
        s.x += v.x; s.y += v.y; s.z += v.z; s.w += v.w;
    }
    float4 inv = make_float4(1.f / s.x, 1.f / s.y, 1.f / s.z, 1.f / s.w);
    ((float4*)d_colinv)[j4] = inv;
}

// ============================================================
// launch
// ============================================================
extern "C" void kernel_launch(void* const* d_in, const int* in_sizes, int n_in,
                              void* d_out, int out_size)
{
    const float* attendee = (const float*)d_in[0];   // [B,H]
    const float* attender = (const float*)d_in[1];   // [B,H]
    const float* W_score  = (const float*)d_in[2];   // [H,H]
    const float* b_score  = (const float*)d_in[3];   // [H]
    const float* W_out    = (const float*)d_in[4];   // [A,2H]
    const float* b_out    = (const float*)d_in[5];   // [A]
    float* out = (float*)d_out;                      // [B,A]

    float* Y   = nullptr; cudaGetSymbolAddress((void**)&Y,   d_Y);
    float* S   = nullptr; cudaGetSymbolAddress((void**)&S,   d_S);
    float* ctx = nullptr; cudaGetSymbolAddress((void**)&ctx, d_ctx);
    float* cin = nullptr; cudaGetSymbolAddress((void**)&cin, d_colinv);

    dim3 thr(256);

    // 1) Y = attendee @ W_score^T + b_score   [8192 x 1024]
    gemm_nt_kernel<<<dim3(HDIM/128, BDIM/128), thr>>>(
        attendee, W_score, Y, HDIM, HDIM, HDIM, HDIM, b_score);

    // 2) S = Y @ attender^T   [8192 x 8192]  (streaming stores)
    gemm_nt_kernel<<<dim3(BDIM/128, BDIM/128), thr>>>(
        Y, attender, S, HDIM, HDIM, HDIM, BDIM, nullptr);

    // 3) column softmax (axis 0): max, exp+sum (in place), 1/sum
    colmax_part_kernel<<<dim3(BDIM/4/256, RSLICE), thr>>>();
    colmax_reduce_kernel<<<dim3(BDIM/4/256), thr>>>();
    expsum_part_kernel<<<dim3(BDIM/4/256, RSLICE), thr>>>();
    colsum_reduce_kernel<<<dim3(BDIM/4/256), thr>>>();

    // 4) ctx[j] = (1/sum_j) * sum_i E[i][j] * attendee[i]   [8192 x 1024]
    gemm_tn_scale_kernel<<<dim3(HDIM/128, BDIM/128), thr>>>(
        S, attendee, ctx, BDIM, BDIM, HDIM, HDIM, cin);

    // 5) out = tanh([attender | ctx] @ W_out^T + b_out)   [8192 x 1024]
    gemm_out_tanh_kernel<<<dim3(ADIM/128, BDIM/128), thr>>>(
        attender, ctx, W_out, b_out, out);
}

// round 6
// speedup vs baseline: 1.6547x; 1.6547x over previous
#include <cuda_runtime.h>
#include <cuda_bf16.h>
#include <math.h>

#define BDIM 8192
#define HDIM 1024
#define ADIM 1024
#define RSLICE 64
#define ROWS_PER_SLICE (BDIM / RSLICE)   // 128

// ---- scratch (device globals: no allocations allowed) ----
__device__ float d_Y[(size_t)BDIM * HDIM];            // 32 MB
__device__ float d_S[(size_t)BDIM * BDIM];            // 256 MB (scores -> exp in place)
__device__ float d_ctx[(size_t)BDIM * HDIM];          // 32 MB
__device__ float d_part[(size_t)RSLICE * BDIM];
__device__ float d_colmax[BDIM];
__device__ float d_colinv[BDIM];
// bf16 split buffers
__device__ __nv_bfloat16 d_Yhi[(size_t)BDIM * HDIM];
__device__ __nv_bfloat16 d_Ylo[(size_t)BDIM * HDIM];
__device__ __nv_bfloat16 d_Rhi[(size_t)BDIM * HDIM];      // attender hi
__device__ __nv_bfloat16 d_Rlo[(size_t)BDIM * HDIM];
__device__ __nv_bfloat16 d_EThi[(size_t)BDIM * BDIM];     // exp(S)^T  128 MB
__device__ __nv_bfloat16 d_ETlo[(size_t)BDIM * BDIM];     // 128 MB
__device__ __nv_bfloat16 d_ADThi[(size_t)HDIM * BDIM];    // attendee^T
__device__ __nv_bfloat16 d_ADTlo[(size_t)HDIM * BDIM];

// ---- packed f32x2 helpers (SIMT path) ----
__device__ __forceinline__ void fma2(unsigned long long& d, unsigned long long a,
                                     unsigned long long b) {
    asm("fma.rn.f32x2 %0, %1, %2, %0;" : "+l"(d) : "l"(a), "l"(b));
}
__device__ __forceinline__ unsigned long long bcast2(float x) {
    unsigned long long r;
    asm("mov.b64 %0, {%1, %1};" : "=l"(r) : "f"(x));
    return r;
}
__device__ __forceinline__ float2 unpack2(unsigned long long v) {
    float2 f;
    asm("mov.b64 {%0, %1}, %2;" : "=f"(f.x), "=f"(f.y) : "l"(v));
    return f;
}
__device__ __forceinline__ void frag_fma(unsigned long long acc2[8][4],
                                         const float* __restrict__ a_ptr,
                                         const float* __restrict__ b_ptr) {
    float4 ta0 = *(const float4*)(a_ptr);
    float4 ta1 = *(const float4*)(a_ptr + 4);
    ulonglong2 tb0 = *(const ulonglong2*)(b_ptr);
    ulonglong2 tb1 = *(const ulonglong2*)(b_ptr + 4);
    unsigned long long b2[4] = {tb0.x, tb0.y, tb1.x, tb1.y};
    float a[8] = {ta0.x, ta0.y, ta0.z, ta0.w, ta1.x, ta1.y, ta1.z, ta1.w};
    #pragma unroll
    for (int i = 0; i < 8; i++) {
        unsigned long long a2 = bcast2(a[i]);
        #pragma unroll
        for (int j = 0; j < 4; j++) fma2(acc2[i][j], a2, b2[j]);
    }
}

// ---- cp.async helpers ----
__device__ __forceinline__ void cp_async16(void* sdst, const void* gsrc) {
    unsigned saddr = (unsigned)__cvta_generic_to_shared(sdst);
    asm volatile("cp.async.cg.shared.global [%0], [%1], 16;\n" :: "r"(saddr), "l"(gsrc));
}
__device__ __forceinline__ void cp_commit() {
    asm volatile("cp.async.commit_group;\n");
}
template<int N> __device__ __forceinline__ void cp_wait() {
    asm volatile("cp.async.wait_group %0;\n" :: "n"(N));
}

// ---- bf16 mma ----
__device__ __forceinline__ void mma16816(float c[4], const unsigned a[4], const unsigned b[2]) {
    asm volatile(
        "mma.sync.aligned.m16n8k16.row.col.f32.bf16.bf16.f32 "
        "{%0,%1,%2,%3}, {%4,%5,%6,%7}, {%8,%9}, {%0,%1,%2,%3};\n"
        : "+f"(c[0]), "+f"(c[1]), "+f"(c[2]), "+f"(c[3])
        : "r"(a[0]), "r"(a[1]), "r"(a[2]), "r"(a[3]), "r"(b[0]), "r"(b[1]));
}

// ============================================================
// Tensor-core NT GEMM with bf16 hi/lo split:
// C[m][n] = (rowscale[m]?) * sum_k (Ahi+Alo)[m][k] * (Bhi+Blo)[n][k]
// BM=BN=128, BK=16, 256 threads, warp grid 2(m) x 4(n), warp tile 64x32.
// SMEM rows padded to 24 bf16 (48B): conflict-free frag loads, 16B cp.async.
// ============================================================
#define SSTR 24
__global__ void __launch_bounds__(256)
mma_nt_split_kernel(const __nv_bfloat16* __restrict__ Ahi, const __nv_bfloat16* __restrict__ Alo,
                    const __nv_bfloat16* __restrict__ Bhi, const __nv_bfloat16* __restrict__ Blo,
                    float* __restrict__ C, int K, int ldc,
                    const float* __restrict__ rowscale, int streaming)
{
    __shared__ __nv_bfloat16 smem[2][4][128 * SSTR];   // Ahi,Alo,Bhi,Blo  (48KB total)
    const int t  = threadIdx.x;
    const int w  = t >> 5, l = t & 31;
    const int wm = w >> 2, wn = w & 3;           // 2 x 4 warp grid
    const int g  = l >> 2, th = l & 3;
    const size_t m0 = (size_t)blockIdx.y * 128;
    const size_t n0 = (size_t)blockIdx.x * 128;

    float acc[4][4][4];
    #pragma unroll
    for (int mt = 0; mt < 4; mt++)
        #pragma unroll
        for (int nt = 0; nt < 4; nt++)
            #pragma unroll
            for (int e = 0; e < 4; e++) acc[mt][nt][e] = 0.f;

    // cp.async mapping: thread -> (row r, 16B-chunk hh) of each of the 4 tiles
    const int r  = t >> 1;
    const int hh = t & 1;
    const __nv_bfloat16* gsrc[4];
    gsrc[0] = Ahi + (m0 + r) * (size_t)K + hh * 8;
    gsrc[1] = Alo + (m0 + r) * (size_t)K + hh * 8;
    gsrc[2] = Bhi + (n0 + r) * (size_t)K + hh * 8;
    gsrc[3] = Blo + (n0 + r) * (size_t)K + hh * 8;
    const int sdst = r * SSTR + hh * 8;

    const int NT = K / 16;

    // prologue: tile 0
    #pragma unroll
    for (int q = 0; q < 4; q++) cp_async16(&smem[0][q][sdst], gsrc[q]);
    cp_commit();

    int buf = 0;
    for (int kt = 0; kt < NT; kt++) {
        if (kt + 1 < NT) {
            int k0 = (kt + 1) * 16;
            #pragma unroll
            for (int q = 0; q < 4; q++) cp_async16(&smem[buf ^ 1][q][sdst], gsrc[q] + k0);
            cp_commit();
            cp_wait<1>();
        } else {
            cp_wait<0>();
        }
        __syncthreads();

        const __nv_bfloat16* sAhi = smem[buf][0];
        const __nv_bfloat16* sAlo = smem[buf][1];
        const __nv_bfloat16* sBhi = smem[buf][2];
        const __nv_bfloat16* sBlo = smem[buf][3];

        unsigned bh[4][2], bl[4][2];
        #pragma unroll
        for (int nt = 0; nt < 4; nt++) {
            int nr = wn * 32 + nt * 8 + g;
            int co = th * 2;
            bh[nt][0] = *(const unsigned*)&sBhi[nr * SSTR + co];
            bh[nt][1] = *(const unsigned*)&sBhi[nr * SSTR + co + 8];
            bl[nt][0] = *(const unsigned*)&sBlo[nr * SSTR + co];
            bl[nt][1] = *(const unsigned*)&sBlo[nr * SSTR + co + 8];
        }
        #pragma unroll
        for (int mt = 0; mt < 4; mt++) {
            int mr = wm * 64 + mt * 16 + g;
            int co = th * 2;
            unsigned ah[4], al[4];
            ah[0] = *(const unsigned*)&sAhi[mr * SSTR + co];
            ah[1] = *(const unsigned*)&sAhi[(mr + 8) * SSTR + co];
            ah[2] = *(const unsigned*)&sAhi[mr * SSTR + co + 8];
            ah[3] = *(const unsigned*)&sAhi[(mr + 8) * SSTR + co + 8];
            al[0] = *(const unsigned*)&sAlo[mr * SSTR + co];
            al[1] = *(const unsigned*)&sAlo[(mr + 8) * SSTR + co];
            al[2] = *(const unsigned*)&sAlo[mr * SSTR + co + 8];
            al[3] = *(const unsigned*)&sAlo[(mr + 8) * SSTR + co + 8];
            #pragma unroll
            for (int nt = 0; nt < 4; nt++) {
                mma16816(acc[mt][nt], ah, bh[nt]);   // hi*hi
                mma16816(acc[mt][nt], ah, bl[nt]);   // hi*lo
                mma16816(acc[mt][nt], al, bh[nt]);   // lo*hi
            }
        }
        __syncthreads();
        buf ^= 1;
    }

    #pragma unroll
    for (int mt = 0; mt < 4; mt++) {
        size_t row = m0 + wm * 64 + mt * 16 + g;
        float s0 = 1.f, s1 = 1.f;
        if (rowscale) { s0 = __ldg(&rowscale[row]); s1 = __ldg(&rowscale[row + 8]); }
        #pragma unroll
        for (int nt = 0; nt < 4; nt++) {
            size_t col = n0 + wn * 32 + nt * 8 + th * 2;
            float2 v0 = make_float2(acc[mt][nt][0] * s0, acc[mt][nt][1] * s0);
            float2 v1 = make_float2(acc[mt][nt][2] * s1, acc[mt][nt][3] * s1);
            if (streaming) {
                __stcs((float2*)&C[row * ldc + col], v0);
                __stcs((float2*)&C[(row + 8) * ldc + col], v1);
            } else {
                *(float2*)&C[row * ldc + col] = v0;
                *(float2*)&C[(row + 8) * ldc + col] = v1;
            }
        }
    }
}

// ============================================================
// fp32 -> bf16 hi/lo split, row-major elementwise
// ============================================================
__global__ void cvt_split_kernel(const float* __restrict__ in,
                                 __nv_bfloat16* __restrict__ hi,
                                 __nv_bfloat16* __restrict__ lo, int n4)
{
    int i = blockIdx.x * blockDim.x + threadIdx.x;
    if (i >= n4) return;
    float4 v = ((const float4*)in)[i];
    float xs[4] = {v.x, v.y, v.z, v.w};
    __nv_bfloat16 h[4], l[4];
    #pragma unroll
    for (int e = 0; e < 4; e++) {
        h[e] = __float2bfloat16(xs[e]);
        l[e] = __float2bfloat16(xs[e] - __bfloat162float(h[e]));
    }
    ((ulonglong1*)hi)[i] = *(ulonglong1*)h;
    ((ulonglong1*)lo)[i] = *(ulonglong1*)l;
}

// ============================================================
// fp32 [R][C] -> bf16 hi/lo TRANSPOSED [C][R].  Tile 64(i) x 128(j).
// ============================================================
__global__ void transpose_cvt_kernel(const float* __restrict__ in,
                                     __nv_bfloat16* __restrict__ hiT,
                                     __nv_bfloat16* __restrict__ loT,
                                     int R, int C)
{
    __shared__ __nv_bfloat162 T[128][65];
    const int t = threadIdx.x;
    const size_t j0 = (size_t)blockIdx.x * 128;
    const size_t i0 = (size_t)blockIdx.y * 64;

    #pragma unroll
    for (int q = 0; q < 8; q++) {
        int idx = q * 256 + t;
        int rr = idx >> 5;
        int c4 = idx & 31;
        float4 v = __ldcs((const float4*)(in + (i0 + rr) * C + j0) + c4);
        float xs[4] = {v.x, v.y, v.z, v.w};
        #pragma unroll
        for (int e = 0; e < 4; e++) {
            __nv_bfloat16 h = __float2bfloat16(xs[e]);
            __nv_bfloat16 l = __float2bfloat16(xs[e] - __bfloat162float(h));
            __nv_bfloat162 p; p.x = h; p.y = l;
            T[c4 * 4 + e][rr] = p;
        }
    }
    __syncthreads();

    #pragma unroll
    for (int q = 0; q < 4; q++) {
        int idx = q * 256 + t;
        int j = idx >> 3;
        int c8 = idx & 7;
        uint4 uh, ul;
        __nv_bfloat16* hs = (__nv_bfloat16*)&uh;
        __nv_bfloat16* ls = (__nv_bfloat16*)&ul;
        #pragma unroll
        for (int e = 0; e < 8; e++) {
            __nv_bfloat162 p = T[j][c8 * 8 + e];
            hs[e] = p.x; ls[e] = p.y;
        }
        size_t off = (j0 + j) * (size_t)R + i0 + c8 * 8;
        *(uint4*)(hiT + off) = uh;
        *(uint4*)(loT + off) = ul;
    }
}

// ============================================================
// SIMT NT GEMM (f32x2) — kept for GEMM1 (Y) only
// ============================================================
__global__ void __launch_bounds__(256, 2)
gemm_nt_kernel(const float* __restrict__ A, const float* __restrict__ B,
               float* __restrict__ C, int K, int lda, int ldb, int ldc,
               const float* __restrict__ bias)
{
    __shared__ float As[2][16][132];
    __shared__ float Bs[2][16][132];
    const int tid = threadIdx.x;
    const int tx = tid & 15;
    const int ty = tid >> 4;
    const int m0 = blockIdx.y * 128;
    const int n0 = blockIdx.x * 128;

    const int r0 = tid >> 2,         c0 = tid & 3;
    const int r1 = (tid + 256) >> 2, c1 = (tid + 256) & 3;

    unsigned long long acc2[8][4];
    const unsigned long long z2 = bcast2(0.f);
    #pragma unroll
    for (int i = 0; i < 8; i++)
        #pragma unroll
        for (int j = 0; j < 4; j++) acc2[i][j] = z2;

    const float* Ap = A + (size_t)m0 * lda;
    const float* Bp = B + (size_t)n0 * ldb;

    float4 pa0, pa1, pb0, pb1;
    pa0 = *(const float4*)(Ap + (size_t)r0 * lda + c0 * 4);
    pa1 = *(const float4*)(Ap + (size_t)r1 * lda + c1 * 4);
    pb0 = *(const float4*)(Bp + (size_t)r0 * ldb + c0 * 4);
    pb1 = *(const float4*)(Bp + (size_t)r1 * ldb + c1 * 4);

    int buf = 0;
    const int NT = K / 16;
    for (int kt = 0; kt < NT; kt++) {
        As[buf][c0*4+0][r0] = pa0.x; As[buf][c0*4+1][r0] = pa0.y;
        As[buf][c0*4+2][r0] = pa0.z; As[buf][c0*4+3][r0] = pa0.w;
        As[buf][c1*4+0][r1] = pa1.x; As[buf][c1*4+1][r1] = pa1.y;
        As[buf][c1*4+2][r1] = pa1.z; As[buf][c1*4+3][r1] = pa1.w;
        Bs[buf][c0*4+0][r0] = pb0.x; Bs[buf][c0*4+1][r0] = pb0.y;
        Bs[buf][c0*4+2][r0] = pb0.z; Bs[buf][c0*4+3][r0] = pb0.w;
        Bs[buf][c1*4+0][r1] = pb1.x; Bs[buf][c1*4+1][r1] = pb1.y;
        Bs[buf][c1*4+2][r1] = pb1.z; Bs[buf][c1*4+3][r1] = pb1.w;
        __syncthreads();

        if (kt + 1 < NT) {
            int k0 = (kt + 1) * 16;
            pa0 = *(const float4*)(Ap + (size_t)r0 * lda + k0 + c0 * 4);
            pa1 = *(const float4*)(Ap + (size_t)r1 * lda + k0 + c1 * 4);
            pb0 = *(const float4*)(Bp + (size_t)r0 * ldb + k0 + c0 * 4);
            pb1 = *(const float4*)(Bp + (size_t)r1 * ldb + k0 + c1 * 4);
        }

        #pragma unroll
        for (int k = 0; k < 16; k++)
            frag_fma(acc2, &As[buf][k][ty*8], &Bs[buf][k][tx*8]);

        buf ^= 1;
    }

    #pragma unroll
    for (int i = 0; i < 8; i++) {
        int m = m0 + ty * 8 + i;
        #pragma unroll
        for (int j = 0; j < 4; j++) {
            int n = n0 + tx * 8 + j * 2;
            float2 v = unpack2(acc2[i][j]);
            v.x += __ldg(&bias[n]); v.y += __ldg(&bias[n + 1]);
            *(float2*)&C[(size_t)m * ldc + n] = v;
        }
    }
}

// ============================================================
// Output GEMM (SIMT f32x2): out = tanh([attender|ctx] @ W^T + b)
// ============================================================
__global__ void __launch_bounds__(256, 2)
gemm_out_tanh_kernel(const float* __restrict__ attender, const float* __restrict__ ctx,
                     const float* __restrict__ W, const float* __restrict__ bias,
                     float* __restrict__ C)
{
    __shared__ float As[2][16][132];
    __shared__ float Bs[2][16][132];
    const int tid = threadIdx.x;
    const int tx = tid & 15;
    const int ty = tid >> 4;
    const int m0 = blockIdx.y * 128;
    const int n0 = blockIdx.x * 128;
    const int K  = 2 * HDIM;

    const int r0 = tid >> 2,         c0 = tid & 3;
    const int r1 = (tid + 256) >> 2, c1 = (tid + 256) & 3;

    unsigned long long acc2[8][4];
    const unsigned long long z2 = bcast2(0.f);
    #pragma unroll
    for (int i = 0; i < 8; i++)
        #pragma unroll
        for (int j = 0; j < 4; j++) acc2[i][j] = z2;

    const float* Wp = W + (size_t)n0 * K;

    float4 pa0, pa1, pb0, pb1;
    pa0 = *(const float4*)(attender + (size_t)(m0 + r0) * HDIM + c0 * 4);
    pa1 = *(const float4*)(attender + (size_t)(m0 + r1) * HDIM + c1 * 4);
    pb0 = *(const float4*)(Wp + (size_t)r0 * K + c0 * 4);
    pb1 = *(const float4*)(Wp + (size_t)r1 * K + c1 * 4);

    int buf = 0;
    const int NT = K / 16;
    for (int kt = 0; kt < NT; kt++) {
        As[buf][c0*4+0][r0] = pa0.x; As[buf][c0*4+1][r0] = pa0.y;
        As[buf][c0*4+2][r0] = pa0.z; As[buf][c0*4+3][r0] = pa0.w;
        As[buf][c1*4+0][r1] = pa1.x; As[buf][c1*4+1][r1] = pa1.y;
        As[buf][c1*4+2][r1] = pa1.z; As[buf][c1*4+3][r1] = pa1.w;
        Bs[buf][c0*4+0][r0] = pb0.x; Bs[buf][c0*4+1][r0] = pb0.y;
        Bs[buf][c0*4+2][r0] = pb0.z; Bs[buf][c0*4+3][r0] = pb0.w;
        Bs[buf][c1*4+0][r1] = pb1.x; Bs[buf][c1*4+1][r1] = pb1.y;
        Bs[buf][c1*4+2][r1] = pb1.z; Bs[buf][c1*4+3][r1] = pb1.w;
        __syncthreads();

        if (kt + 1 < NT) {
            int k0 = (kt + 1) * 16;
            const float* Asrc; int koff;
            if (k0 < HDIM) { Asrc = attender; koff = k0; }
            else           { Asrc = ctx;      koff = k0 - HDIM; }
            pa0 = *(const float4*)(Asrc + (size_t)(m0 + r0) * HDIM + koff + c0 * 4);
            pa1 = *(const float4*)(Asrc + (size_t)(m0 + r1) * HDIM + koff + c1 * 4);
            pb0 = *(const float4*)(Wp + (size_t)r0 * K + k0 + c0 * 4);
            pb1 = *(const float4*)(Wp + (size_t)r1 * K + k0 + c1 * 4);
        }

        #pragma unroll
        for (int k = 0; k < 16; k++)
            frag_fma(acc2, &As[buf][k][ty*8], &Bs[buf][k][tx*8]);

        buf ^= 1;
    }

    #pragma unroll
    for (int i = 0; i < 8; i++) {
        int m = m0 + ty * 8 + i;
        #pragma unroll
        for (int j = 0; j < 4; j++) {
            int n = n0 + tx * 8 + j * 2;
            float2 v = unpack2(acc2[i][j]);
            v.x = tanhf(v.x + __ldg(&bias[n]));
            v.y = tanhf(v.y + __ldg(&bias[n + 1]));
            *(float2*)&C[(size_t)m * ADIM + n] = v;
        }
    }
}

// ============================================================
// Column softmax pieces (unchanged)
// ============================================================
__global__ void colmax_part_kernel()
{
    int j4 = blockIdx.x * blockDim.x + threadIdx.x;
    int ys = blockIdx.y;
    size_t base = ((size_t)ys * ROWS_PER_SLICE * BDIM) / 4 + j4;
    const float4* S4 = (const float4*)d_S;
    float4 m = make_float4(-INFINITY, -INFINITY, -INFINITY, -INFINITY);
    for (int i = 0; i < ROWS_PER_SLICE; i++) {
        float4 v = __ldcs(&S4[base + (size_t)i * (BDIM / 4)]);
        m.x = fmaxf(m.x, v.x); m.y = fmaxf(m.y, v.y);
        m.z = fmaxf(m.z, v.z); m.w = fmaxf(m.w, v.w);
    }
    ((float4*)d_part)[(size_t)ys * (BDIM / 4) + j4] = m;
}

__global__ void colmax_reduce_kernel()
{
    int j4 = blockIdx.x * blockDim.x + threadIdx.x;
    const float4* P4 = (const float4*)d_part;
    float4 m = make_float4(-INFINITY, -INFINITY, -INFINITY, -INFINITY);
    #pragma unroll 8
    for (int r = 0; r < RSLICE; r++) {
        float4 v = P4[(size_t)r * (BDIM / 4) + j4];
        m.x = fmaxf(m.x, v.x); m.y = fmaxf(m.y, v.y);
        m.z = fmaxf(m.z, v.z); m.w = fmaxf(m.w, v.w);
    }
    ((float4*)d_colmax)[j4] = m;
}

__global__ void expsum_part_kernel()
{
    int j4 = blockIdx.x * blockDim.x + threadIdx.x;
    int ys = blockIdx.y;
    float4* S4 = (float4*)d_S;
    size_t base = ((size_t)ys * ROWS_PER_SLICE * BDIM) / 4 + j4;
    float4 mx = ((const float4*)d_colmax)[j4];
    float4 s = make_float4(0.f, 0.f, 0.f, 0.f);
    for (int i = 0; i < ROWS_PER_SLICE; i++) {
        size_t idx = base + (size_t)i * (BDIM / 4);
        float4 v = __ldcs(&S4[idx]);
        v.x = __expf(v.x - mx.x); v.y = __expf(v.y - mx.y);
        v.z = __expf(v.z - mx.z); v.w = __expf(v.w - mx.w);
        S4[idx] = v;
        s.x += v.x; s.y += v.y; s.z += v.z; s.w += v.w;
    }
    ((float4*)d_part)[(size_t)ys * (BDIM / 4) + j4] = s;
}

__global__ void colsum_reduce_kernel()
{
    int j4 = blockIdx.x * blockDim.x + threadIdx.x;
    const float4* P4 = (const float4*)d_part;
    float4 s = make_float4(0.f, 0.f, 0.f, 0.f);
    #pragma unroll 8
    for (int r = 0; r < RSLICE; r++) {
        float4 v = P4[(size_t)r * (BDIM / 4) + j4];
        s.x += v.x; s.y += v.y; s.z += v.z; s.w += v.w;
    }
    float4 inv = make_float4(1.f / s.x, 1.f / s.y, 1.f / s.z, 1.f / s.w);
    ((float4*)d_colinv)[j4] = inv;
}

// ============================================================
// launch
// ============================================================
extern "C" void kernel_launch(void* const* d_in, const int* in_sizes, int n_in,
                              void* d_out, int out_size)
{
    const float* attendee = (const float*)d_in[0];   // [B,H]
    const float* attender = (const float*)d_in[1];   // [B,H]
    const float* W_score  = (const float*)d_in[2];   // [H,H]
    const float* b_score  = (const float*)d_in[3];   // [H]
    const float* W_out    = (const float*)d_in[4];   // [A,2H]
    const float* b_out    = (const float*)d_in[5];   // [A]
    float* out = (float*)d_out;                      // [B,A]

    float* Y   = nullptr; cudaGetSymbolAddress((void**)&Y,   d_Y);
    float* S   = nullptr; cudaGetSymbolAddress((void**)&S,   d_S);
    float* ctx = nullptr; cudaGetSymbolAddress((void**)&ctx, d_ctx);
    float* cin = nullptr; cudaGetSymbolAddress((void**)&cin, d_colinv);
    __nv_bfloat16 *Yhi, *Ylo, *Rhi, *Rlo, *EThi, *ETlo, *ADThi, *ADTlo;
    cudaGetSymbolAddress((void**)&Yhi,  d_Yhi);  cudaGetSymbolAddress((void**)&Ylo,  d_Ylo);
    cudaGetSymbolAddress((void**)&Rhi,  d_Rhi);  cudaGetSymbolAddress((void**)&Rlo,  d_Rlo);
    cudaGetSymbolAddress((void**)&EThi, d_EThi); cudaGetSymbolAddress((void**)&ETlo, d_ETlo);
    cudaGetSymbolAddress((void**)&ADThi,d_ADThi);cudaGetSymbolAddress((void**)&ADTlo,d_ADTlo);

    dim3 thr(256);

    // 1) Y = attendee @ W_score^T + b_score   (SIMT)
    gemm_nt_kernel<<<dim3(HDIM/128, BDIM/128), thr>>>(
        attendee, W_score, Y, HDIM, HDIM, HDIM, HDIM, b_score);

    // 2) splits: Y, attender (row-major); attendee (transposed)
    int n4 = BDIM * HDIM / 4;
    cvt_split_kernel<<<n4 / 256, thr>>>(Y, Yhi, Ylo, n4);
    cvt_split_kernel<<<n4 / 256, thr>>>(attender, Rhi, Rlo, n4);
    transpose_cvt_kernel<<<dim3(HDIM/128, BDIM/64), thr>>>(attendee, ADThi, ADTlo, BDIM, HDIM);

    // 3) S = Y @ attender^T   (tensor, split)  [8192 x 8192]
    mma_nt_split_kernel<<<dim3(BDIM/128, BDIM/128), thr>>>(
        Yhi, Ylo, Rhi, Rlo, S, HDIM, BDIM, nullptr, 1);

    // 4) column softmax: max, exp+sum (in place fp32), 1/sum
    colmax_part_kernel<<<dim3(BDIM/4/256, RSLICE), thr>>>();
    colmax_reduce_kernel<<<dim3(BDIM/4/256), thr>>>();
    expsum_part_kernel<<<dim3(BDIM/4/256, RSLICE), thr>>>();
    colsum_reduce_kernel<<<dim3(BDIM/4/256), thr>>>();

    // 5) E^T split (transpose 256MB exp(S) -> bf16 hi/lo)
    transpose_cvt_kernel<<<dim3(BDIM/128, BDIM/64), thr>>>(S, EThi, ETlo, BDIM, BDIM);

    // 6) ctx[j][h] = colinv[j] * sum_i E[i][j]*attendee[i][h]   (tensor, split)
    mma_nt_split_kernel<<<dim3(HDIM/128, BDIM/128), thr>>>(
        EThi, ETlo, ADThi, ADTlo, ctx, BDIM, HDIM, cin, 0);

    // 7) out = tanh([attender | ctx] @ W_out^T + b_out)   (SIMT)
    gemm_out_tanh_kernel<<<dim3(ADIM/128, BDIM/128), thr>>>(
        attender, ctx, W_out, b_out, out);
}

// round 8
// speedup vs baseline: 1.9901x; 1.2027x over previous
#include <cuda_runtime.h>
#include <cuda_bf16.h>
#include <math.h>

#define BDIM 8192
#define HDIM 1024
#define ADIM 1024
#define RSLICE 64          // colmax slices (GEMM2 grid.y)
#define RS2 128            // colsum slices (exp-transpose grid.y)

// ---- scratch (device globals: no allocations allowed) ----
__device__ float d_S[(size_t)BDIM * BDIM];            // 256 MB raw scores
__device__ float d_part[(size_t)RSLICE * BDIM];       // colmax partials
__device__ float d_part2[(size_t)RS2 * BDIM];         // colsum partials
__device__ float d_colmax[BDIM];
__device__ float d_colinv[BDIM];
// bf16 split buffers
__device__ __nv_bfloat16 d_ADhi[(size_t)BDIM * HDIM];     // attendee row-major
__device__ __nv_bfloat16 d_ADlo[(size_t)BDIM * HDIM];
__device__ __nv_bfloat16 d_Rhi[(size_t)BDIM * HDIM];      // attender
__device__ __nv_bfloat16 d_Rlo[(size_t)BDIM * HDIM];
__device__ __nv_bfloat16 d_WShi[(size_t)HDIM * HDIM];     // W_score
__device__ __nv_bfloat16 d_WSlo[(size_t)HDIM * HDIM];
__device__ __nv_bfloat16 d_WOhi[(size_t)ADIM * 2 * HDIM]; // W_out
__device__ __nv_bfloat16 d_WOlo[(size_t)ADIM * 2 * HDIM];
__device__ __nv_bfloat16 d_Yhi[(size_t)BDIM * HDIM];
__device__ __nv_bfloat16 d_Ylo[(size_t)BDIM * HDIM];
__device__ __nv_bfloat16 d_EThi[(size_t)BDIM * BDIM];     // exp(S)^T 128 MB
__device__ __nv_bfloat16 d_ETlo[(size_t)BDIM * BDIM];
__device__ __nv_bfloat16 d_ADThi[(size_t)HDIM * BDIM];    // attendee^T
__device__ __nv_bfloat16 d_ADTlo[(size_t)HDIM * BDIM];
__device__ __nv_bfloat16 d_CXhi[(size_t)BDIM * HDIM];     // ctx splits
__device__ __nv_bfloat16 d_CXlo[(size_t)BDIM * HDIM];

// ---- cp.async helpers ----
__device__ __forceinline__ void cp_async16(void* sdst, const void* gsrc) {
    unsigned saddr = (unsigned)__cvta_generic_to_shared(sdst);
    asm volatile("cp.async.cg.shared.global [%0], [%1], 16;\n" :: "r"(saddr), "l"(gsrc));
}
__device__ __forceinline__ void cp_commit() {
    asm volatile("cp.async.commit_group;\n");
}
template<int N> __device__ __forceinline__ void cp_wait() {
    asm volatile("cp.async.wait_group %0;\n" :: "n"(N));
}

// ---- bf16 mma ----
__device__ __forceinline__ void mma16816(float c[4], const unsigned a[4], const unsigned b[2]) {
    asm volatile(
        "mma.sync.aligned.m16n8k16.row.col.f32.bf16.bf16.f32 "
        "{%0,%1,%2,%3}, {%4,%5,%6,%7}, {%8,%9}, {%0,%1,%2,%3};\n"
        : "+f"(c[0]), "+f"(c[1]), "+f"(c[2]), "+f"(c[3])
        : "r"(a[0]), "r"(a[1]), "r"(a[2]), "r"(a[3]), "r"(b[0]), "r"(b[1]));
}

__device__ __forceinline__ void split_bf16(float x, __nv_bfloat16& h, __nv_bfloat16& l) {
    h = __float2bfloat16(x);
    l = __float2bfloat16(x - __bfloat162float(h));
}

// ============================================================
// Tensor-core NT GEMM with bf16 hi/lo split.
// C = sum_k (Ahi+Alo)[m][k]*(Bhi+Blo)[n][k]; row stride of A,B == K.
// BM=BN=128, BK=16, 256 thr, warps 2(m)x4(n), warp tile 64x32.
// mode 0: fp32 streaming store to Cf[ldc] + per-block colmax -> partmax
// mode 1: v = acc*rowscale[m]; split store to Chi/Clo [ldc]
// mode 2: v = acc+bias[n];     split store to Chi/Clo [ldc]
// ============================================================
#define SSTR 24
__global__ void __launch_bounds__(256)
mma_nt_split_kernel(const __nv_bfloat16* __restrict__ Ahi, const __nv_bfloat16* __restrict__ Alo,
                    const __nv_bfloat16* __restrict__ Bhi, const __nv_bfloat16* __restrict__ Blo,
                    int K, int mode,
                    float* __restrict__ Cf, __nv_bfloat16* __restrict__ Chi,
                    __nv_bfloat16* __restrict__ Clo, int ldc,
                    const float* __restrict__ rowscale, const float* __restrict__ bias,
                    float* __restrict__ partmax)
{
    __shared__ __nv_bfloat16 smem[2][4][128 * SSTR];   // 48KB
    const int t  = threadIdx.x;
    const int w  = t >> 5, l = t & 31;
    const int wm = w >> 2, wn = w & 3;
    const int g  = l >> 2, th = l & 3;
    const size_t m0 = (size_t)blockIdx.y * 128;
    const size_t n0 = (size_t)blockIdx.x * 128;

    float acc[4][4][4];
    #pragma unroll
    for (int mt = 0; mt < 4; mt++)
        #pragma unroll
        for (int nt = 0; nt < 4; nt++)
            #pragma unroll
            for (int e = 0; e < 4; e++) acc[mt][nt][e] = 0.f;

    const int r  = t >> 1;
    const int hh = t & 1;
    const __nv_bfloat16* gsrc[4];
    gsrc[0] = Ahi + (m0 + r) * (size_t)K + hh * 8;
    gsrc[1] = Alo + (m0 + r) * (size_t)K + hh * 8;
    gsrc[2] = Bhi + (n0 + r) * (size_t)K + hh * 8;
    gsrc[3] = Blo + (n0 + r) * (size_t)K + hh * 8;
    const int sdst = r * SSTR + hh * 8;

    const int NT = K / 16;
    #pragma unroll
    for (int q = 0; q < 4; q++) cp_async16(&smem[0][q][sdst], gsrc[q]);
    cp_commit();

    int buf = 0;
    for (int kt = 0; kt < NT; kt++) {
        if (kt + 1 < NT) {
            int k0 = (kt + 1) * 16;
            #pragma unroll
            for (int q = 0; q < 4; q++) cp_async16(&smem[buf ^ 1][q][sdst], gsrc[q] + k0);
            cp_commit();
            cp_wait<1>();
        } else {
            cp_wait<0>();
        }
        __syncthreads();

        const __nv_bfloat16* sAhi = smem[buf][0];
        const __nv_bfloat16* sAlo = smem[buf][1];
        const __nv_bfloat16* sBhi = smem[buf][2];
        const __nv_bfloat16* sBlo = smem[buf][3];

        unsigned bh[4][2], bl[4][2];
        #pragma unroll
        for (int nt = 0; nt < 4; nt++) {
            int nr = wn * 32 + nt * 8 + g;
            int co = th * 2;
            bh[nt][0] = *(const unsigned*)&sBhi[nr * SSTR + co];
            bh[nt][1] = *(const unsigned*)&sBhi[nr * SSTR + co + 8];
            bl[nt][0] = *(const unsigned*)&sBlo[nr * SSTR + co];
            bl[nt][1] = *(const unsigned*)&sBlo[nr * SSTR + co + 8];
        }
        #pragma unroll
        for (int mt = 0; mt < 4; mt++) {
            int mr = wm * 64 + mt * 16 + g;
            int co = th * 2;
            unsigned ah[4], al[4];
            ah[0] = *(const unsigned*)&sAhi[mr * SSTR + co];
            ah[1] = *(const unsigned*)&sAhi[(mr + 8) * SSTR + co];
            ah[2] = *(const unsigned*)&sAhi[mr * SSTR + co + 8];
            ah[3] = *(const unsigned*)&sAhi[(mr + 8) * SSTR + co + 8];
            al[0] = *(const unsigned*)&sAlo[mr * SSTR + co];
            al[1] = *(const unsigned*)&sAlo[(mr + 8) * SSTR + co];
            al[2] = *(const unsigned*)&sAlo[mr * SSTR + co + 8];
            al[3] = *(const unsigned*)&sAlo[(mr + 8) * SSTR + co + 8];
            #pragma unroll
            for (int nt = 0; nt < 4; nt++) {
                mma16816(acc[mt][nt], ah, bh[nt]);
                mma16816(acc[mt][nt], ah, bl[nt]);
                mma16816(acc[mt][nt], al, bh[nt]);
            }
        }
        __syncthreads();
        buf ^= 1;
    }

    if (mode == 0) {
        // fp32 streaming store + fused per-block column max
        #pragma unroll
        for (int mt = 0; mt < 4; mt++) {
            size_t row = m0 + wm * 64 + mt * 16 + g;
            #pragma unroll
            for (int nt = 0; nt < 4; nt++) {
                size_t col = n0 + wn * 32 + nt * 8 + th * 2;
                __stcs((float2*)&Cf[row * ldc + col],
                       make_float2(acc[mt][nt][0], acc[mt][nt][1]));
                __stcs((float2*)&Cf[(row + 8) * ldc + col],
                       make_float2(acc[mt][nt][2], acc[mt][nt][3]));
            }
        }
        // reuse pipeline smem (all reads done; loop ended with __syncthreads)
        float* cmaxS = (float*)&smem[0][0][0];   // [16][128] floats = 8KB
        #pragma unroll
        for (int nt = 0; nt < 4; nt++) {
            #pragma unroll
            for (int e = 0; e < 2; e++) {
                int c = wn * 32 + nt * 8 + th * 2 + e;
                float m = -INFINITY;
                #pragma unroll
                for (int mt = 0; mt < 4; mt++)
                    m = fmaxf(m, fmaxf(acc[mt][nt][e], acc[mt][nt][e + 2]));
                cmaxS[(wm * 8 + g) * 128 + c] = m;
            }
        }
        __syncthreads();
        if (t < 128) {
            float m = -INFINITY;
            #pragma unroll
            for (int s = 0; s < 16; s++) m = fmaxf(m, cmaxS[s * 128 + t]);
            partmax[(size_t)blockIdx.y * BDIM + n0 + t] = m;
        }
    } else if (mode == 1) {
        #pragma unroll
        for (int mt = 0; mt < 4; mt++) {
            size_t row = m0 + wm * 64 + mt * 16 + g;
            float s0 = __ldg(&rowscale[row]);
            float s1 = __ldg(&rowscale[row + 8]);
            #pragma unroll
            for (int nt = 0; nt < 4; nt++) {
                size_t col = n0 + wn * 32 + nt * 8 + th * 2;
                __nv_bfloat162 h, lo2;
                split_bf16(acc[mt][nt][0] * s0, h.x, lo2.x);
                split_bf16(acc[mt][nt][1] * s0, h.y, lo2.y);
                *(__nv_bfloat162*)&Chi[row * ldc + col] = h;
                *(__nv_bfloat162*)&Clo[row * ldc + col] = lo2;
                split_bf16(acc[mt][nt][2] * s1, h.x, lo2.x);
                split_bf16(acc[mt][nt][3] * s1, h.y, lo2.y);
                *(__nv_bfloat162*)&Chi[(row + 8) * ldc + col] = h;
                *(__nv_bfloat162*)&Clo[(row + 8) * ldc + col] = lo2;
            }
        }
    } else {
        #pragma unroll
        for (int mt = 0; mt < 4; mt++) {
            size_t row = m0 + wm * 64 + mt * 16 + g;
            #pragma unroll
            for (int nt = 0; nt < 4; nt++) {
                size_t col = n0 + wn * 32 + nt * 8 + th * 2;
                float b0 = __ldg(&bias[col]), b1 = __ldg(&bias[col + 1]);
                __nv_bfloat162 h, lo2;
                split_bf16(acc[mt][nt][0] + b0, h.x, lo2.x);
                split_bf16(acc[mt][nt][1] + b1, h.y, lo2.y);
                *(__nv_bfloat162*)&Chi[row * ldc + col] = h;
                *(__nv_bfloat162*)&Clo[row * ldc + col] = lo2;
                split_bf16(acc[mt][nt][2] + b0, h.x, lo2.x);
                split_bf16(acc[mt][nt][3] + b1, h.y, lo2.y);
                *(__nv_bfloat162*)&Chi[(row + 8) * ldc + col] = h;
                *(__nv_bfloat162*)&Clo[(row + 8) * ldc + col] = lo2;
            }
        }
    }
}

// ============================================================
// Output GEMM (tensor, concat A): out[m][n] = tanh(acc + bias[n])
// A = [attender | ctx] splits, K = 2048, source switch at k=1024.
// ============================================================
__global__ void __launch_bounds__(256)
mma_out_split_kernel(const __nv_bfloat16* __restrict__ A1hi, const __nv_bfloat16* __restrict__ A1lo,
                     const __nv_bfloat16* __restrict__ A2hi, const __nv_bfloat16* __restrict__ A2lo,
                     const __nv_bfloat16* __restrict__ Bhi, const __nv_bfloat16* __restrict__ Blo,
                     const float* __restrict__ bias, float* __restrict__ C)
{
    __shared__ __nv_bfloat16 smem[2][4][128 * SSTR];
    const int t  = threadIdx.x;
    const int w  = t >> 5, l = t & 31;
    const int wm = w >> 2, wn = w & 3;
    const int g  = l >> 2, th = l & 3;
    const size_t m0 = (size_t)blockIdx.y * 128;
    const size_t n0 = (size_t)blockIdx.x * 128;
    const int K = 2 * HDIM;

    float acc[4][4][4];
    #pragma unroll
    for (int mt = 0; mt < 4; mt++)
        #pragma unroll
        for (int nt = 0; nt < 4; nt++)
            #pragma unroll
            for (int e = 0; e < 4; e++) acc[mt][nt][e] = 0.f;

    const int r  = t >> 1;
    const int hh = t & 1;
    const size_t aoff = (m0 + r) * (size_t)HDIM + hh * 8;
    const __nv_bfloat16* gB0 = Bhi + (n0 + r) * (size_t)K + hh * 8;
    const __nv_bfloat16* gB1 = Blo + (n0 + r) * (size_t)K + hh * 8;
    const int sdst = r * SSTR + hh * 8;

    const int NT = K / 16;
    // prologue (k0 = 0 -> attender)
    cp_async16(&smem[0][0][sdst], A1hi + aoff);
    cp_async16(&smem[0][1][sdst], A1lo + aoff);
    cp_async16(&smem[0][2][sdst], gB0);
    cp_async16(&smem[0][3][sdst], gB1);
    cp_commit();

    int buf = 0;
    for (int kt = 0; kt < NT; kt++) {
        if (kt + 1 < NT) {
            int k0 = (kt + 1) * 16;
            const __nv_bfloat16 *ah, *al;
            if (k0 < HDIM) { ah = A1hi + aoff + k0; al = A1lo + aoff + k0; }
            else           { ah = A2hi + aoff + (k0 - HDIM); al = A2lo + aoff + (k0 - HDIM); }
            cp_async16(&smem[buf ^ 1][0][sdst], ah);
            cp_async16(&smem[buf ^ 1][1][sdst], al);
            cp_async16(&smem[buf ^ 1][2][sdst], gB0 + k0);
            cp_async16(&smem[buf ^ 1][3][sdst], gB1 + k0);
            cp_commit();
            cp_wait<1>();
        } else {
            cp_wait<0>();
        }
        __syncthreads();

        const __nv_bfloat16* sAhi = smem[buf][0];
        const __nv_bfloat16* sAlo = smem[buf][1];
        const __nv_bfloat16* sBhi = smem[buf][2];
        const __nv_bfloat16* sBlo = smem[buf][3];

        unsigned bh[4][2], bl[4][2];
        #pragma unroll
        for (int nt = 0; nt < 4; nt++) {
            int nr = wn * 32 + nt * 8 + g;
            int co = th * 2;
            bh[nt][0] = *(const unsigned*)&sBhi[nr * SSTR + co];
            bh[nt][1] = *(const unsigned*)&sBhi[nr * SSTR + co + 8];
            bl[nt][0] = *(const unsigned*)&sBlo[nr * SSTR + co];
            bl[nt][1] = *(const unsigned*)&sBlo[nr * SSTR + co + 8];
        }
        #pragma unroll
        for (int mt = 0; mt < 4; mt++) {
            int mr = wm * 64 + mt * 16 + g;
            int co = th * 2;
            unsigned ah[4], al[4];
            ah[0] = *(const unsigned*)&sAhi[mr * SSTR + co];
            ah[1] = *(const unsigned*)&sAhi[(mr + 8) * SSTR + co];
            ah[2] = *(const unsigned*)&sAhi[mr * SSTR + co + 8];
            ah[3] = *(const unsigned*)&sAhi[(mr + 8) * SSTR + co + 8];
            al[0] = *(const unsigned*)&sAlo[mr * SSTR + co];
            al[1] = *(const unsigned*)&sAlo[(mr + 8) * SSTR + co];
            al[2] = *(const unsigned*)&sAlo[mr * SSTR + co + 8];
            al[3] = *(const unsigned*)&sAlo[(mr + 8) * SSTR + co + 8];
            #pragma unroll
            for (int nt = 0; nt < 4; nt++) {
                mma16816(acc[mt][nt], ah, bh[nt]);
                mma16816(acc[mt][nt], ah, bl[nt]);
                mma16816(acc[mt][nt], al, bh[nt]);
            }
        }
        __syncthreads();
        buf ^= 1;
    }

    #pragma unroll
    for (int mt = 0; mt < 4; mt++) {
        size_t row = m0 + wm * 64 + mt * 16 + g;
        #pragma unroll
        for (int nt = 0; nt < 4; nt++) {
            size_t col = n0 + wn * 32 + nt * 8 + th * 2;
            float b0 = __ldg(&bias[col]), b1 = __ldg(&bias[col + 1]);
            *(float2*)&C[row * ADIM + col] =
                make_float2(tanhf(acc[mt][nt][0] + b0), tanhf(acc[mt][nt][1] + b1));
            *(float2*)&C[(row + 8) * ADIM + col] =
                make_float2(tanhf(acc[mt][nt][2] + b0), tanhf(acc[mt][nt][3] + b1));
        }
    }
}

// ============================================================
// fp32 -> bf16 hi/lo split, row-major elementwise
// ============================================================
__global__ void cvt_split_kernel(const float* __restrict__ in,
                                 __nv_bfloat16* __restrict__ hi,
                                 __nv_bfloat16* __restrict__ lo, int n4)
{
    int i = blockIdx.x * blockDim.x + threadIdx.x;
    if (i >= n4) return;
    float4 v = ((const float4*)in)[i];
    float xs[4] = {v.x, v.y, v.z, v.w};
    __nv_bfloat16 h[4], l[4];
    #pragma unroll
    for (int e = 0; e < 4; e++) split_bf16(xs[e], h[e], l[e]);
    ((ulonglong1*)hi)[i] = *(ulonglong1*)h;
    ((ulonglong1*)lo)[i] = *(ulonglong1*)l;
}

// ============================================================
// fp32 [R][C] -> bf16 hi/lo TRANSPOSED [C][R]. Tile 64(i) x 128(j).
// ============================================================
__global__ void transpose_cvt_kernel(const float* __restrict__ in,
                                     __nv_bfloat16* __restrict__ hiT,
                                     __nv_bfloat16* __restrict__ loT,
                                     int R, int C)
{
    __shared__ __nv_bfloat162 T[128][65];
    const int t = threadIdx.x;
    const size_t j0 = (size_t)blockIdx.x * 128;
    const size_t i0 = (size_t)blockIdx.y * 64;
    const int c4 = t & 31;
    const int wrp = t >> 5;

    #pragma unroll
    for (int q = 0; q < 8; q++) {
        int rr = q * 8 + wrp;
        float4 v = __ldcs((const float4*)(in + (i0 + rr) * C + j0) + c4);
        float xs[4] = {v.x, v.y, v.z, v.w};
        #pragma unroll
        for (int e = 0; e < 4; e++) {
            __nv_bfloat162 p;
            split_bf16(xs[e], p.x, p.y);
            T[c4 * 4 + e][rr] = p;
        }
    }
    __syncthreads();

    #pragma unroll
    for (int q = 0; q < 4; q++) {
        int idx = q * 256 + t;
        int j = idx >> 3;
        int c8 = idx & 7;
        uint4 uh, ul;
        __nv_bfloat16* hs = (__nv_bfloat16*)&uh;
        __nv_bfloat16* ls = (__nv_bfloat16*)&ul;
        #pragma unroll
        for (int e = 0; e < 8; e++) {
            __nv_bfloat162 p = T[j][c8 * 8 + e];
            hs[e] = p.x; ls[e] = p.y;
        }
        size_t off = (j0 + j) * (size_t)R + i0 + c8 * 8;
        *(uint4*)(hiT + off) = uh;
        *(uint4*)(loT + off) = ul;
    }
}

// ============================================================
// exp + transpose + split + partial column sums, for S (scores).
// Reads raw scores, computes e=exp(s - colmax[j]), writes ET hi/lo
// transposed, and d_part2[iblock][j] = sum over the 64 rows.
// Tile 64(i) x 128(j); grid (BDIM/128, BDIM/64).
// ============================================================
__global__ void exp_transpose_kernel(const float* __restrict__ in,
                                     __nv_bfloat16* __restrict__ hiT,
                                     __nv_bfloat16* __restrict__ loT)
{
    __shared__ __nv_bfloat162 T[128][65];
    __shared__ float ssum[8][132];
    const int t = threadIdx.x;
    const size_t j0 = (size_t)blockIdx.x * 128;
    const size_t i0 = (size_t)blockIdx.y * 64;
    const int c4 = t & 31;        // fixed float4-column per thread
    const int wrp = t >> 5;

    float4 mx = *(const float4*)(d_colmax + j0 + c4 * 4);
    float4 s = make_float4(0.f, 0.f, 0.f, 0.f);

    #pragma unroll
    for (int q = 0; q < 8; q++) {
        int rr = q * 8 + wrp;     // rows 0..63
        float4 v = __ldcs((const float4*)(in + (i0 + rr) * BDIM + j0) + c4);
        float es[4];
        es[0] = __expf(v.x - mx.x); es[1] = __expf(v.y - mx.y);
        es[2] = __expf(v.z - mx.z); es[3] = __expf(v.w - mx.w);
        s.x += es[0]; s.y += es[1]; s.z += es[2]; s.w += es[3];
        #pragma unroll
        for (int e = 0; e < 4; e++) {
            __nv_bfloat162 p;
            split_bf16(es[e], p.x, p.y);
            T[c4 * 4 + e][rr] = p;
        }
    }
    ssum[wrp][c4 * 4 + 0] = s.x;
    ssum[wrp][c4 * 4 + 1] = s.y;
    ssum[wrp][c4 * 4 + 2] = s.z;
    ssum[wrp][c4 * 4 + 3] = s.w;
    __syncthreads();

    if (t < 128) {
        float acc = 0.f;
        #pragma unroll
        for (int w2 = 0; w2 < 8; w2++) acc += ssum[w2][t];
        d_part2[(size_t)blockIdx.y * BDIM + j0 + t] = acc;
    }

    #pragma unroll
    for (int q = 0; q < 4; q++) {
        int idx = q * 256 + t;
        int j = idx >> 3;
        int c8 = idx & 7;
        uint4 uh, ul;
        __nv_bfloat16* hs = (__nv_bfloat16*)&uh;
        __nv_bfloat16* ls = (__nv_bfloat16*)&ul;
        #pragma unroll
        for (int e = 0; e < 8; e++) {
            __nv_bfloat162 p = T[j][c8 * 8 + e];
            hs[e] = p.x; ls[e] = p.y;
        }
        size_t off = (j0 + j) * (size_t)BDIM + i0 + c8 * 8;
        *(uint4*)(hiT + off) = uh;
        *(uint4*)(loT + off) = ul;
    }
}

// ============================================================
// reductions over slices
// ============================================================
__global__ void colmax_reduce_kernel()
{
    int j4 = blockIdx.x * blockDim.x + threadIdx.x;
    const float4* P4 = (const float4*)d_part;
    float4 m = make_float4(-INFINITY, -INFINITY, -INFINITY, -INFINITY);
    #pragma unroll 8
    for (int r = 0; r < RSLICE; r++) {
        float4 v = P4[(size_t)r * (BDIM / 4) + j4];
        m.x = fmaxf(m.x, v.x); m.y = fmaxf(m.y, v.y);
        m.z = fmaxf(m.z, v.z); m.w = fmaxf(m.w, v.w);
    }
    ((float4*)d_colmax)[j4] = m;
}

__global__ void colsum_reduce_kernel()
{
    int j4 = blockIdx.x * blockDim.x + threadIdx.x;
    const float4* P4 = (const float4*)d_part2;
    float4 s = make_float4(0.f, 0.f, 0.f, 0.f);
    #pragma unroll 8
    for (int r = 0; r < RS2; r++) {
        float4 v = P4[(size_t)r * (BDIM / 4) + j4];
        s.x += v.x; s.y += v.y; s.z += v.z; s.w += v.w;
    }
    float4 inv = make_float4(1.f / s.x, 1.f / s.y, 1.f / s.z, 1.f / s.w);
    ((float4*)d_colinv)[j4] = inv;
}

// ============================================================
// launch
// ============================================================
extern "C" void kernel_launch(void* const* d_in, const int* in_sizes, int n_in,
                              void* d_out, int out_size)
{
    const float* attendee = (const float*)d_in[0];   // [B,H]
    const float* attender = (const float*)d_in[1];   // [B,H]
    const float* W_score  = (const float*)d_in[2];   // [H,H]
    const float* b_score  = (const float*)d_in[3];   // [H]
    const float* W_out    = (const float*)d_in[4];   // [A,2H]
    const float* b_out    = (const float*)d_in[5];   // [A]
    float* out = (float*)d_out;                      // [B,A]

    float *S, *cmx_part, *cin;
    cudaGetSymbolAddress((void**)&S, d_S);
    cudaGetSymbolAddress((void**)&cmx_part, d_part);
    cudaGetSymbolAddress((void**)&cin, d_colinv);
    __nv_bfloat16 *ADhi, *ADlo, *Rhi, *Rlo, *WShi, *WSlo, *WOhi, *WOlo;
    __nv_bfloat16 *Yhi, *Ylo, *EThi, *ETlo, *ADThi, *ADTlo, *CXhi, *CXlo;
    cudaGetSymbolAddress((void**)&ADhi, d_ADhi);  cudaGetSymbolAddress((void**)&ADlo, d_ADlo);
    cudaGetSymbolAddress((void**)&Rhi,  d_Rhi);   cudaGetSymbolAddress((void**)&Rlo,  d_Rlo);
    cudaGetSymbolAddress((void**)&WShi, d_WShi);  cudaGetSymbolAddress((void**)&WSlo, d_WSlo);
    cudaGetSymbolAddress((void**)&WOhi, d_WOhi);  cudaGetSymbolAddress((void**)&WOlo, d_WOlo);
    cudaGetSymbolAddress((void**)&Yhi,  d_Yhi);   cudaGetSymbolAddress((void**)&Ylo,  d_Ylo);
    cudaGetSymbolAddress((void**)&EThi, d_EThi);  cudaGetSymbolAddress((void**)&ETlo, d_ETlo);
    cudaGetSymbolAddress((void**)&ADThi,d_ADThi); cudaGetSymbolAddress((void**)&ADTlo,d_ADTlo);
    cudaGetSymbolAddress((void**)&CXhi, d_CXhi);  cudaGetSymbolAddress((void**)&CXlo, d_CXlo);

    dim3 thr(256);

    // 0) input splits
    cvt_split_kernel<<<BDIM * HDIM / 4 / 256, thr>>>(attendee, ADhi, ADlo, BDIM * HDIM / 4);
    cvt_split_kernel<<<BDIM * HDIM / 4 / 256, thr>>>(attender, Rhi, Rlo, BDIM * HDIM / 4);
    cvt_split_kernel<<<HDIM * HDIM / 4 / 256, thr>>>(W_score, WShi, WSlo, HDIM * HDIM / 4);
    cvt_split_kernel<<<ADIM * 2 * HDIM / 4 / 256, thr>>>(W_out, WOhi, WOlo, ADIM * 2 * HDIM / 4);
    transpose_cvt_kernel<<<dim3(HDIM / 128, BDIM / 64), thr>>>(attendee, ADThi, ADTlo, BDIM, HDIM);

    // 1) Y = attendee @ W_score^T + b_score  -> bf16 splits directly
    mma_nt_split_kernel<<<dim3(HDIM / 128, BDIM / 128), thr>>>(
        ADhi, ADlo, WShi, WSlo, HDIM, 2, nullptr, Yhi, Ylo, HDIM, nullptr, b_score, nullptr);

    // 2) S = Y @ attender^T (fp32 streaming) + fused colmax partials
    mma_nt_split_kernel<<<dim3(BDIM / 128, BDIM / 128), thr>>>(
        Yhi, Ylo, Rhi, Rlo, HDIM, 0, S, nullptr, nullptr, BDIM, nullptr, nullptr, cmx_part);

    // 3) colmax reduce
    colmax_reduce_kernel<<<BDIM / 4 / 256, thr>>>();

    // 4) exp + transpose + split + colsum partials
    exp_transpose_kernel<<<dim3(BDIM / 128, BDIM / 64), thr>>>(S, EThi, ETlo);

    // 5) colsum reduce -> 1/sum
    colsum_reduce_kernel<<<BDIM / 4 / 256, thr>>>();

    // 6) ctx = colinv ⊙ (E^T @ attendee) -> bf16 splits directly
    mma_nt_split_kernel<<<dim3(HDIM / 128, BDIM / 128), thr>>>(
        EThi, ETlo, ADThi, ADTlo, BDIM, 1, nullptr, CXhi, CXlo, HDIM, cin, nullptr, nullptr);

    // 7) out = tanh([attender | ctx] @ W_out^T + b_out)
    mma_out_split_kernel<<<dim3(ADIM / 128, BDIM / 128), thr>>>(
        Rhi, Rlo, CXhi, CXlo, WOhi, WOlo, b_out, out);
}